// round 15
// baseline (speedup 1.0000x reference)
#include <cuda_runtime.h>
#include <math.h>

#define H 4096
#define GRID 256
#define THREADS 512
#define RPB 16           // rows per block (one per warp)
#define NMAX 16
#define THRESH 0.99f     // 1 - EPS

#define CK 256           // chunk: floats per row per stage
#define NCHUNK (H / CK)  // 16
#define DEPTH 2          // pipeline depth

#define PIN_IN_CHUNKS 8     // W_ih: first 8 of 16 chunks pinned -> 33.5 MB
#define PIN_OUT_BLKS 320    // W_out: first 320 of 512 8-float blocks pinned -> 41.9 MB
// total pinned = 75.4 MB (measured retention saturation point)

#define WO_CACHE_BLKS 128   // streamed W_out blocks cached in smem per row (4KB/row)
// W_out block map per row: [0,320) pinned L2 | [320,448) smem-cached | [448,512) tail LDG

// dynamic smem layout (floats): X[4096] | S[4096] | bufI[DEPTH*RPB*CK] | bufH[DEPTH*RPB*CK]
#define SMEM_FLOATS (2 * H + 2 * DEPTH * RPB * CK)

// ---- scratch (no allocations allowed) ----
__device__ float g_u0[H];          // W_ih@x0 + b_ih + b_hh (steps t>=1)
__device__ float g_sbuf[2][H];     // ping-pong hidden state
__device__ float g_hpart[2][GRID]; // per-block halt-dot partials (ping-pong)
__device__ unsigned g_barcount = 0;
__device__ unsigned g_bargen = 0;

// 256-bit pinned load: L2::evict_last
__device__ __forceinline__ void ldg256_keep(const float* __restrict__ p, float v[8]) {
    unsigned r0, r1, r2, r3, r4, r5, r6, r7;
    asm volatile("ld.global.nc.L2::evict_last.v8.b32 {%0,%1,%2,%3,%4,%5,%6,%7}, [%8];"
                 : "=r"(r0), "=r"(r1), "=r"(r2), "=r"(r3),
                   "=r"(r4), "=r"(r5), "=r"(r6), "=r"(r7)
                 : "l"(p));
    v[0] = __uint_as_float(r0); v[1] = __uint_as_float(r1);
    v[2] = __uint_as_float(r2); v[3] = __uint_as_float(r3);
    v[4] = __uint_as_float(r4); v[5] = __uint_as_float(r5);
    v[6] = __uint_as_float(r6); v[7] = __uint_as_float(r7);
}
// 256-bit streamed load: L2::evict_first
__device__ __forceinline__ void ldg256_stream(const float* __restrict__ p, float v[8]) {
    unsigned r0, r1, r2, r3, r4, r5, r6, r7;
    asm volatile("ld.global.nc.L2::evict_first.v8.b32 {%0,%1,%2,%3,%4,%5,%6,%7}, [%8];"
                 : "=r"(r0), "=r"(r1), "=r"(r2), "=r"(r3),
                   "=r"(r4), "=r"(r5), "=r"(r6), "=r"(r7)
                 : "l"(p));
    v[0] = __uint_as_float(r0); v[1] = __uint_as_float(r1);
    v[2] = __uint_as_float(r2); v[3] = __uint_as_float(r3);
    v[4] = __uint_as_float(r4); v[5] = __uint_as_float(r5);
    v[6] = __uint_as_float(r6); v[7] = __uint_as_float(r7);
}

// cp.async 16B with an L2 cache-hint policy
__device__ __forceinline__ void cp16(unsigned smem_addr, const float* __restrict__ g,
                                     unsigned long long pol) {
    asm volatile("cp.async.cg.shared.global.L2::cache_hint [%0], [%1], 16, %2;"
                 :: "r"(smem_addr), "l"(g), "l"(pol) : "memory");
}
__device__ __forceinline__ void cp_commit() {
    asm volatile("cp.async.commit_group;" ::: "memory");
}
template <int N>
__device__ __forceinline__ void cp_wait() {
    asm volatile("cp.async.wait_group %0;" :: "n"(N) : "memory");
}

// grid-wide barrier (all GRID blocks co-resident: 2 CTA/SM x 148 SM = 296 >= 256)
__device__ __forceinline__ void gbar() {
    __syncthreads();
    if (threadIdx.x == 0) {
        __threadfence();
        unsigned gen = *(volatile unsigned*)&g_bargen;
        if (atomicAdd(&g_barcount, 1u) == GRID - 1u) {
            g_barcount = 0u;
            __threadfence();
            atomicExch(&g_bargen, gen + 1u);
        } else {
            while (*(volatile unsigned*)&g_bargen == gen) { }
            __threadfence();
        }
    }
    __syncthreads();
}

// single-stream warp dot, evict-first LDG.128 (rare t>=1 path); result in ALL lanes
__device__ __forceinline__ float warpdot8(const float* __restrict__ w,
                                          const float4* __restrict__ sv) {
    const float4* wr = (const float4*)w;
    const int lane = threadIdx.x & 31;
    float acc = 0.f;
#pragma unroll 8
    for (int i = lane; i < H / 4; i += 32) {
        float4 a = __ldcs(wr + i);
        float4 b = sv[i];
        acc = fmaf(a.x, b.x, acc);
        acc = fmaf(a.y, b.y, acc);
        acc = fmaf(a.z, b.z, acc);
        acc = fmaf(a.w, b.w, acc);
    }
#pragma unroll
    for (int o = 16; o > 0; o >>= 1) acc += __shfl_xor_sync(0xffffffffu, acc, o);
    return acc;
}

__device__ __forceinline__ float fma8v(const float a[8], const float4* sv, int i, float acc) {
    float4 b0 = sv[2 * i];
    float4 b1 = sv[2 * i + 1];
    acc = fmaf(a[0], b0.x, acc);
    acc = fmaf(a[1], b0.y, acc);
    acc = fmaf(a[2], b0.z, acc);
    acc = fmaf(a[3], b0.w, acc);
    acc = fmaf(a[4], b1.x, acc);
    acc = fmaf(a[5], b1.y, acc);
    acc = fmaf(a[6], b1.z, acc);
    acc = fmaf(a[7], b1.w, acc);
    return acc;
}

__global__ void __launch_bounds__(THREADS, 2) skiparnn_kernel(
    const float* __restrict__ x,     const float* __restrict__ s0,
    const float* __restrict__ y0,    const float* __restrict__ h0,
    const float* __restrict__ W_ih,  const float* __restrict__ b_ih,
    const float* __restrict__ W_hh,  const float* __restrict__ b_hh,
    const float* __restrict__ W_halt,const float* __restrict__ b_halt,
    const float* __restrict__ W_out, const float* __restrict__ b_out,
    float* __restrict__ out)
{
    extern __shared__ __align__(16) float dyn[];
    float* smemX = dyn;                 // [H]
    float* smemS = dyn + H;             // [H]
    float* bufI  = dyn + 2 * H;                     // [DEPTH][RPB][CK] (phase A) / W_out cache (phase B)
    float* bufH  = dyn + 2 * H + DEPTH * RPB * CK;  // [DEPTH][RPB][CK]
    __shared__ float sh_hp[RPB];

    const int tid  = threadIdx.x;
    const int warp = tid >> 5;
    const int lane = tid & 31;
    const int bid  = blockIdx.x;
    const int r    = bid * RPB + warp;          // this warp's row (0..4095)

    const float h0v = h0[0];
    if (h0v >= THRESH) {
        int g = bid * THREADS + tid;
        if (g < H) { out[g] = y0[g]; out[H + g] = s0[g]; }
        if (g == 0) { out[2 * H] = 0.f; out[2 * H + 1] = h0v - 1.f; }
        return;
    }

    unsigned long long polKeep, polStream;
    asm volatile("createpolicy.fractional.L2::evict_last.b64 %0, 1.0;" : "=l"(polKeep));
    asm volatile("createpolicy.fractional.L2::evict_first.b64 %0, 1.0;" : "=l"(polStream));

    // ---- step 0: cp.async depth-2 pipelined dual matvec ----
    {
        const float* wi = W_ih + (size_t)r * H;
        const float* wh = W_hh + (size_t)r * H;
        unsigned bI = (unsigned)__cvta_generic_to_shared(bufI + warp * CK);
        unsigned bH = (unsigned)__cvta_generic_to_shared(bufH + warp * CK);
        const unsigned slotStride = RPB * CK * 4u;   // bytes per slot

        // prologue FIRST (doesn't need smemX/S): stages 0..DEPTH-1 in flight early
#pragma unroll
        for (int c = 0; c < DEPTH; c++) {
            int slot = c;
            unsigned long long pI = (c < PIN_IN_CHUNKS) ? polKeep : polStream;
#pragma unroll
            for (int k = 0; k < CK / 128; k++) {
                int j = k * 32 + lane;
                cp16(bI + slot * slotStride + j * 16u, wi + c * CK + j * 4, pI);
                cp16(bH + slot * slotStride + j * 16u, wh + c * CK + j * 4, polStream);
            }
            cp_commit();
        }

        // stage x1 and s0 into shared (overlaps with in-flight cp.async)
        for (int i = tid; i < H; i += THREADS) {
            smemX[i] = (i == 0) ? 1.f : x[i - 1];
            smemS[i] = s0[i];
        }
        __syncthreads();

        float accI = 0.f, accH = 0.f;
        const float4* sx4 = (const float4*)smemX;
        const float4* ss4 = (const float4*)smemS;
        const float4* bI4 = (const float4*)(bufI + warp * CK);
        const float4* bH4 = (const float4*)(bufH + warp * CK);
        const int slotStride4 = RPB * CK / 4;      // float4 per slot

        for (int c = 0; c < NCHUNK; c++) {
            cp_wait<DEPTH - 1>();                  // stage c complete (per-thread)
            int slot = c % DEPTH;
#pragma unroll
            for (int k = 0; k < CK / 128; k++) {
                int j = k * 32 + lane;             // float4 index within chunk
                float4 a  = bI4[slot * slotStride4 + j];
                float4 b  = bH4[slot * slotStride4 + j];
                float4 xv = sx4[c * (CK / 4) + j];
                float4 sv = ss4[c * (CK / 4) + j];
                accI = fmaf(a.x, xv.x, accI);
                accI = fmaf(a.y, xv.y, accI);
                accI = fmaf(a.z, xv.z, accI);
                accI = fmaf(a.w, xv.w, accI);
                accH = fmaf(b.x, sv.x, accH);
                accH = fmaf(b.y, sv.y, accH);
                accH = fmaf(b.z, sv.z, accH);
                accH = fmaf(b.w, sv.w, accH);
            }
            int cn = c + DEPTH;
            if (cn < NCHUNK) {
                int ns = cn % DEPTH;
                unsigned long long pI = (cn < PIN_IN_CHUNKS) ? polKeep : polStream;
#pragma unroll
                for (int k = 0; k < CK / 128; k++) {
                    int j = k * 32 + lane;
                    cp16(bI + ns * slotStride + j * 16u, wi + cn * CK + j * 4, pI);
                    cp16(bH + ns * slotStride + j * 16u, wh + cn * CK + j * 4, polStream);
                }
            }
            cp_commit();                           // keep group count advancing
        }
        cp_wait<0>();

#pragma unroll
        for (int o = 16; o > 0; o >>= 1) {
            accI += __shfl_xor_sync(0xffffffffu, accI, o);
            accH += __shfl_xor_sync(0xffffffffu, accH, o);
        }
        float bias = b_ih[r] + b_hh[r];
        float snew = tanhf(accI + bias + accH);
        if (lane == 0) {
            // W_ih@x0 = W_ih@x1 - W_ih[:,0]
            g_u0[r]      = accI - __ldg(W_ih + (size_t)r * H) + bias;
            g_sbuf[0][r] = snew;
            sh_hp[warp]  = snew * __ldg(W_halt + r);
        }
    }
    __syncthreads();   // phase-A smem reads done block-wide; buf is now dead

    // ---- issue W_out streamed-slice cache fills into the dead pipeline smem ----
    // These DRAM requests queue behind phase A and drain during the reduction /
    // barrier / halt-decision window (otherwise DRAM-idle time).
    {
        const float* wo = W_out + (size_t)r * H;
        unsigned wreg = (unsigned)__cvta_generic_to_shared(bufI) + (unsigned)warp * 4096u;
#pragma unroll
        for (int tloop = 0; tloop < WO_CACHE_BLKS / 32; tloop++) {
            int b = tloop * 32 + lane;                       // cached block (local)
            const float* src = wo + (size_t)(PIN_OUT_BLKS + b) * 8;
            cp16(wreg + (unsigned)b * 32u,       src,     polStream);
            cp16(wreg + (unsigned)b * 32u + 16u, src + 4, polStream);
        }
        cp_commit();
    }

    if (tid == 0) {
        float hp = 0.f;
#pragma unroll
        for (int i = 0; i < RPB; i++) hp += sh_hp[i];
        g_hpart[0][bid] = hp;
    }
    gbar();

    float acc    = h0v;
    float ponder = 0.f;
    const float bh = b_halt[0];
    int   t = 0;
    int   haltstep = -1;
    float lastacc  = 0.f;

    while (true) {
        // unconditional copy of the current state into smemS — needed by BOTH paths
        for (int i = tid; i < H; i += THREADS) smemS[i] = g_sbuf[t & 1][i];

        // deterministic fixed-order reduction of halt-dot partials (same in all blocks)
        float hd;
        {
            const float* hp = g_hpart[t & 1];
            float a = 0.f;
#pragma unroll
            for (int i = lane; i < GRID; i += 32) a += hp[i];
#pragma unroll
            for (int o = 16; o > 0; o >>= 1) a += __shfl_xor_sync(0xffffffffu, a, o);
            hd = a;
        }
        float accNew = acc + 2.f / (1.f + expf(-(hd + bh)));
        __syncthreads();                            // smemS ready
        if (accNew >= THRESH) { haltstep = t; lastacc = accNew; break; }
        ponder += 1.f;
        acc = accNew;
        if (t == NMAX - 1) break;

        // ---- step t+1: z = u0 + W_hh @ s (streamed; rare path) ----
        float z    = g_u0[r] + warpdot8(W_hh + (size_t)r * H, (const float4*)smemS);
        float snew = tanhf(z);
        if (lane == 0) {
            g_sbuf[(t + 1) & 1][r] = snew;
            sh_hp[warp]            = snew * __ldg(W_halt + r);
        }
        __syncthreads();
        if (tid == 0) {
            float hp = 0.f;
#pragma unroll
            for (int i = 0; i < RPB; i++) hp += sh_hp[i];
            g_hpart[(t + 1) & 1][bid] = hp;
        }
        t++;
        gbar();
    }

    if (haltstep >= 0) {
        // y = W_out @ s_halt + b_out ; smemS holds s_halt; bufI holds cached blocks
        const float*  wo  = W_out + (size_t)r * H;
        const float4* sv  = (const float4*)smemS;
        float acc2 = 0.f;
        // 1) tail streamed blocks [PIN+CACHE, 512): misses issue earliest
        for (int i = PIN_OUT_BLKS + WO_CACHE_BLKS + lane; i < H / 8; i += 32) {
            float a[8];
            ldg256_stream(wo + (size_t)i * 8, a);
            acc2 = fma8v(a, sv, i, acc2);
        }
        // 2) pinned blocks [0, PIN): L2-resident reads overlap the tail misses
#pragma unroll 4
        for (int i = lane; i < PIN_OUT_BLKS; i += 32) {
            float a[8];
            ldg256_keep(wo + (size_t)i * 8, a);
            acc2 = fma8v(a, sv, i, acc2);
        }
        // 3) smem-cached blocks [PIN, PIN+CACHE): wait for the overlap fills, read smem
        cp_wait<0>();
        {
            const float4* reg4 = (const float4*)(bufI + warp * 1024);
#pragma unroll
            for (int tloop = 0; tloop < WO_CACHE_BLKS / 32; tloop++) {
                int b = tloop * 32 + lane;
                float4 a0 = reg4[2 * b];
                float4 a1 = reg4[2 * b + 1];
                int i = PIN_OUT_BLKS + b;
                float4 b0 = sv[2 * i];
                float4 b1 = sv[2 * i + 1];
                acc2 = fmaf(a0.x, b0.x, acc2);
                acc2 = fmaf(a0.y, b0.y, acc2);
                acc2 = fmaf(a0.z, b0.z, acc2);
                acc2 = fmaf(a0.w, b0.w, acc2);
                acc2 = fmaf(a1.x, b1.x, acc2);
                acc2 = fmaf(a1.y, b1.y, acc2);
                acc2 = fmaf(a1.z, b1.z, acc2);
                acc2 = fmaf(a1.w, b1.w, acc2);
            }
        }
#pragma unroll
        for (int o = 16; o > 0; o >>= 1) acc2 += __shfl_xor_sync(0xffffffffu, acc2, o);
        float yv = acc2 + b_out[r];
        if (lane == 0) {
            out[r]     = yv;
            out[H + r] = smemS[r];
        }
        if (bid == 0 && tid == 0) {
            out[2 * H]     = ponder;           // = haltstep = n-1
            out[2 * H + 1] = lastacc - 1.f;
        }
    } else {
        // never halted within 16 steps: halt_bin all zero
        cp_wait<0>();                           // drain W_out cache fills before exit
        int g = bid * THREADS + tid;
        if (g < H) { out[g] = 0.f; out[H + g] = 0.f; }
        if (g == 0) { out[2 * H] = ponder; out[2 * H + 1] = -1.f; }
    }
}

extern "C" void kernel_launch(void* const* d_in, const int* in_sizes, int n_in,
                              void* d_out, int out_size) {
    (void)in_sizes; (void)n_in; (void)out_size;
    // idempotent attribute set (not an allocation; safe pre-capture and in capture)
    cudaFuncSetAttribute(skiparnn_kernel,
                         cudaFuncAttributeMaxDynamicSharedMemorySize,
                         SMEM_FLOATS * (int)sizeof(float));
    skiparnn_kernel<<<GRID, THREADS, SMEM_FLOATS * sizeof(float)>>>(
        (const float*)d_in[0],  (const float*)d_in[1],
        (const float*)d_in[2],  (const float*)d_in[3],
        (const float*)d_in[4],  (const float*)d_in[5],
        (const float*)d_in[6],  (const float*)d_in[7],
        (const float*)d_in[8],  (const float*)d_in[9],
        (const float*)d_in[10], (const float*)d_in[11],
        (float*)d_out);
}

// round 16
// speedup vs baseline: 1.0653x; 1.0653x over previous
#include <cuda_runtime.h>
#include <math.h>

#define H 4096
#define GRID 256
#define THREADS 512
#define RPB 16           // rows per block (one per warp)
#define NMAX 16
#define THRESH 0.99f     // 1 - EPS

#define CK 256           // chunk: floats per row per stage
#define NCHUNK (H / CK)  // 16
#define DEPTH 2          // pipeline depth

#define PIN_IN_CHUNKS 8     // W_ih: first 8 of 16 chunks pinned -> 33.5 MB
#define PIN_OUT_BLKS 320    // W_out: first 320 of 512 8-float blocks pinned -> 41.9 MB
// total pinned = 75.4 MB (measured retention saturation point)

// dynamic smem layout (floats): X[4096] | S[4096] | bufI[DEPTH*RPB*CK] | bufH[DEPTH*RPB*CK]
#define SMEM_FLOATS (2 * H + 2 * DEPTH * RPB * CK)

// ---- scratch (no allocations allowed) ----
__device__ float g_u0[H];          // W_ih@x0 + b_ih + b_hh (steps t>=1)
__device__ float g_sbuf[2][H];     // ping-pong hidden state
__device__ float g_hpart[2][GRID]; // per-block halt-dot partials (ping-pong)
__device__ unsigned g_barcount = 0;
__device__ unsigned g_bargen = 0;

// 256-bit pinned load: L2::evict_last
__device__ __forceinline__ void ldg256_keep(const float* __restrict__ p, float v[8]) {
    unsigned r0, r1, r2, r3, r4, r5, r6, r7;
    asm volatile("ld.global.nc.L2::evict_last.v8.b32 {%0,%1,%2,%3,%4,%5,%6,%7}, [%8];"
                 : "=r"(r0), "=r"(r1), "=r"(r2), "=r"(r3),
                   "=r"(r4), "=r"(r5), "=r"(r6), "=r"(r7)
                 : "l"(p));
    v[0] = __uint_as_float(r0); v[1] = __uint_as_float(r1);
    v[2] = __uint_as_float(r2); v[3] = __uint_as_float(r3);
    v[4] = __uint_as_float(r4); v[5] = __uint_as_float(r5);
    v[6] = __uint_as_float(r6); v[7] = __uint_as_float(r7);
}
// 256-bit streamed load: L2::evict_first
__device__ __forceinline__ void ldg256_stream(const float* __restrict__ p, float v[8]) {
    unsigned r0, r1, r2, r3, r4, r5, r6, r7;
    asm volatile("ld.global.nc.L2::evict_first.v8.b32 {%0,%1,%2,%3,%4,%5,%6,%7}, [%8];"
                 : "=r"(r0), "=r"(r1), "=r"(r2), "=r"(r3),
                   "=r"(r4), "=r"(r5), "=r"(r6), "=r"(r7)
                 : "l"(p));
    v[0] = __uint_as_float(r0); v[1] = __uint_as_float(r1);
    v[2] = __uint_as_float(r2); v[3] = __uint_as_float(r3);
    v[4] = __uint_as_float(r4); v[5] = __uint_as_float(r5);
    v[6] = __uint_as_float(r6); v[7] = __uint_as_float(r7);
}

// cp.async 16B with an L2 cache-hint policy
__device__ __forceinline__ void cp16(unsigned smem_addr, const float* __restrict__ g,
                                     unsigned long long pol) {
    asm volatile("cp.async.cg.shared.global.L2::cache_hint [%0], [%1], 16, %2;"
                 :: "r"(smem_addr), "l"(g), "l"(pol) : "memory");
}
__device__ __forceinline__ void cp_commit() {
    asm volatile("cp.async.commit_group;" ::: "memory");
}
template <int N>
__device__ __forceinline__ void cp_wait() {
    asm volatile("cp.async.wait_group %0;" :: "n"(N) : "memory");
}

// grid-wide barrier (all GRID blocks co-resident: 2 CTA/SM x 148 SM = 296 >= 256)
__device__ __forceinline__ void gbar() {
    __syncthreads();
    if (threadIdx.x == 0) {
        __threadfence();
        unsigned gen = *(volatile unsigned*)&g_bargen;
        if (atomicAdd(&g_barcount, 1u) == GRID - 1u) {
            g_barcount = 0u;
            __threadfence();
            atomicExch(&g_bargen, gen + 1u);
        } else {
            while (*(volatile unsigned*)&g_bargen == gen) { }
            __threadfence();
        }
    }
    __syncthreads();
}

// single-stream warp dot, evict-first LDG.128 (rare t>=1 path); result in ALL lanes
__device__ __forceinline__ float warpdot8(const float* __restrict__ w,
                                          const float4* __restrict__ sv) {
    const float4* wr = (const float4*)w;
    const int lane = threadIdx.x & 31;
    float acc = 0.f;
#pragma unroll 8
    for (int i = lane; i < H / 4; i += 32) {
        float4 a = __ldcs(wr + i);
        float4 b = sv[i];
        acc = fmaf(a.x, b.x, acc);
        acc = fmaf(a.y, b.y, acc);
        acc = fmaf(a.z, b.z, acc);
        acc = fmaf(a.w, b.w, acc);
    }
#pragma unroll
    for (int o = 16; o > 0; o >>= 1) acc += __shfl_xor_sync(0xffffffffu, acc, o);
    return acc;
}

__device__ __forceinline__ float fma8v(const float a[8], const float4* sv, int i, float acc) {
    float4 b0 = sv[2 * i];
    float4 b1 = sv[2 * i + 1];
    acc = fmaf(a[0], b0.x, acc);
    acc = fmaf(a[1], b0.y, acc);
    acc = fmaf(a[2], b0.z, acc);
    acc = fmaf(a[3], b0.w, acc);
    acc = fmaf(a[4], b1.x, acc);
    acc = fmaf(a[5], b1.y, acc);
    acc = fmaf(a[6], b1.z, acc);
    acc = fmaf(a[7], b1.w, acc);
    return acc;
}

// W_out warp dot: streamed (DRAM) tail FIRST so its misses issue earliest and
// overlap the pinned (L2-resident) reads that follow. Same traffic, better overlap.
__device__ __forceinline__ float warpdot_out(const float* __restrict__ w,
                                             const float4* __restrict__ sv) {
    const int lane = threadIdx.x & 31;
    float acc = 0.f;
    for (int i = PIN_OUT_BLKS + lane; i < H / 8; i += 32) {
        float a[8];
        ldg256_stream(w + (size_t)i * 8, a);
        acc = fma8v(a, sv, i, acc);
    }
#pragma unroll 4
    for (int i = lane; i < PIN_OUT_BLKS; i += 32) {
        float a[8];
        ldg256_keep(w + (size_t)i * 8, a);
        acc = fma8v(a, sv, i, acc);
    }
#pragma unroll
    for (int o = 16; o > 0; o >>= 1) acc += __shfl_xor_sync(0xffffffffu, acc, o);
    return acc;
}

__global__ void __launch_bounds__(THREADS, 2) skiparnn_kernel(
    const float* __restrict__ x,     const float* __restrict__ s0,
    const float* __restrict__ y0,    const float* __restrict__ h0,
    const float* __restrict__ W_ih,  const float* __restrict__ b_ih,
    const float* __restrict__ W_hh,  const float* __restrict__ b_hh,
    const float* __restrict__ W_halt,const float* __restrict__ b_halt,
    const float* __restrict__ W_out, const float* __restrict__ b_out,
    float* __restrict__ out)
{
    extern __shared__ __align__(16) float dyn[];
    float* smemX = dyn;                 // [H]
    float* smemS = dyn + H;             // [H]
    float* bufI  = dyn + 2 * H;                     // [DEPTH][RPB][CK]
    float* bufH  = dyn + 2 * H + DEPTH * RPB * CK;  // [DEPTH][RPB][CK]
    __shared__ float sh_hp[RPB];

    const int tid  = threadIdx.x;
    const int warp = tid >> 5;
    const int lane = tid & 31;
    const int bid  = blockIdx.x;
    const int r    = bid * RPB + warp;          // this warp's row (0..4095)

    const float h0v = h0[0];
    if (h0v >= THRESH) {
        int g = bid * THREADS + tid;
        if (g < H) { out[g] = y0[g]; out[H + g] = s0[g]; }
        if (g == 0) { out[2 * H] = 0.f; out[2 * H + 1] = h0v - 1.f; }
        return;
    }

    // ---- step 0: cp.async depth-2 pipelined dual matvec ----
    {
        unsigned long long polKeep, polStream;
        asm volatile("createpolicy.fractional.L2::evict_last.b64 %0, 1.0;" : "=l"(polKeep));
        asm volatile("createpolicy.fractional.L2::evict_first.b64 %0, 1.0;" : "=l"(polStream));

        const float* wi = W_ih + (size_t)r * H;
        const float* wh = W_hh + (size_t)r * H;
        unsigned bI = (unsigned)__cvta_generic_to_shared(bufI + warp * CK);
        unsigned bH = (unsigned)__cvta_generic_to_shared(bufH + warp * CK);
        const unsigned slotStride = RPB * CK * 4u;   // bytes per slot

        // prologue FIRST (doesn't need smemX/S): stages 0..DEPTH-1 in flight early
#pragma unroll
        for (int c = 0; c < DEPTH; c++) {
            int slot = c;
            unsigned long long pI = (c < PIN_IN_CHUNKS) ? polKeep : polStream;
#pragma unroll
            for (int k = 0; k < CK / 128; k++) {
                int j = k * 32 + lane;
                cp16(bI + slot * slotStride + j * 16u, wi + c * CK + j * 4, pI);
                cp16(bH + slot * slotStride + j * 16u, wh + c * CK + j * 4, polStream);
            }
            cp_commit();
        }

        // stage x1 and s0 into shared (overlaps with in-flight cp.async)
        for (int i = tid; i < H; i += THREADS) {
            smemX[i] = (i == 0) ? 1.f : x[i - 1];
            smemS[i] = s0[i];
        }
        __syncthreads();

        float accI = 0.f, accH = 0.f;
        const float4* sx4 = (const float4*)smemX;
        const float4* ss4 = (const float4*)smemS;
        const float4* bI4 = (const float4*)(bufI + warp * CK);
        const float4* bH4 = (const float4*)(bufH + warp * CK);
        const int slotStride4 = RPB * CK / 4;      // float4 per slot

        for (int c = 0; c < NCHUNK; c++) {
            cp_wait<DEPTH - 1>();                  // stage c complete (per-thread)
            int slot = c % DEPTH;
#pragma unroll
            for (int k = 0; k < CK / 128; k++) {
                int j = k * 32 + lane;             // float4 index within chunk
                float4 a  = bI4[slot * slotStride4 + j];
                float4 b  = bH4[slot * slotStride4 + j];
                float4 xv = sx4[c * (CK / 4) + j];
                float4 sv = ss4[c * (CK / 4) + j];
                accI = fmaf(a.x, xv.x, accI);
                accI = fmaf(a.y, xv.y, accI);
                accI = fmaf(a.z, xv.z, accI);
                accI = fmaf(a.w, xv.w, accI);
                accH = fmaf(b.x, sv.x, accH);
                accH = fmaf(b.y, sv.y, accH);
                accH = fmaf(b.z, sv.z, accH);
                accH = fmaf(b.w, sv.w, accH);
            }
            int cn = c + DEPTH;
            if (cn < NCHUNK) {
                int ns = cn % DEPTH;
                unsigned long long pI = (cn < PIN_IN_CHUNKS) ? polKeep : polStream;
#pragma unroll
                for (int k = 0; k < CK / 128; k++) {
                    int j = k * 32 + lane;
                    cp16(bI + ns * slotStride + j * 16u, wi + cn * CK + j * 4, pI);
                    cp16(bH + ns * slotStride + j * 16u, wh + cn * CK + j * 4, polStream);
                }
            }
            cp_commit();                           // keep group count advancing
        }
        cp_wait<0>();

#pragma unroll
        for (int o = 16; o > 0; o >>= 1) {
            accI += __shfl_xor_sync(0xffffffffu, accI, o);
            accH += __shfl_xor_sync(0xffffffffu, accH, o);
        }
        float bias = b_ih[r] + b_hh[r];
        float snew = tanhf(accI + bias + accH);
        if (lane == 0) {
            // W_ih@x0 = W_ih@x1 - W_ih[:,0]
            g_u0[r]      = accI - __ldg(W_ih + (size_t)r * H) + bias;
            g_sbuf[0][r] = snew;
            sh_hp[warp]  = snew * __ldg(W_halt + r);
        }
    }
    __syncthreads();
    if (tid == 0) {
        float hp = 0.f;
#pragma unroll
        for (int i = 0; i < RPB; i++) hp += sh_hp[i];
        g_hpart[0][bid] = hp;
    }
    gbar();

    float acc    = h0v;
    float ponder = 0.f;
    const float bh = b_halt[0];
    int   t = 0;
    int   haltstep = -1;
    float lastacc  = 0.f;

    while (true) {
        // unconditional copy of the current state into smemS — needed by BOTH paths
        for (int i = tid; i < H; i += THREADS) smemS[i] = g_sbuf[t & 1][i];

        // deterministic fixed-order reduction of halt-dot partials (same in all blocks)
        float hd;
        {
            const float* hp = g_hpart[t & 1];
            float a = 0.f;
#pragma unroll
            for (int i = lane; i < GRID; i += 32) a += hp[i];
#pragma unroll
            for (int o = 16; o > 0; o >>= 1) a += __shfl_xor_sync(0xffffffffu, a, o);
            hd = a;
        }
        float accNew = acc + 2.f / (1.f + expf(-(hd + bh)));
        __syncthreads();                            // smemS ready
        if (accNew >= THRESH) { haltstep = t; lastacc = accNew; break; }
        ponder += 1.f;
        acc = accNew;
        if (t == NMAX - 1) break;

        // ---- step t+1: z = u0 + W_hh @ s (streamed; rare path) ----
        float z    = g_u0[r] + warpdot8(W_hh + (size_t)r * H, (const float4*)smemS);
        float snew = tanhf(z);
        if (lane == 0) {
            g_sbuf[(t + 1) & 1][r] = snew;
            sh_hp[warp]            = snew * __ldg(W_halt + r);
        }
        __syncthreads();
        if (tid == 0) {
            float hp = 0.f;
#pragma unroll
            for (int i = 0; i < RPB; i++) hp += sh_hp[i];
            g_hpart[(t + 1) & 1][bid] = hp;
        }
        t++;
        gbar();
    }

    if (haltstep >= 0) {
        // y = W_out @ s_halt + b_out ; smemS already holds s_halt
        float yv = warpdot_out(W_out + (size_t)r * H, (const float4*)smemS) + b_out[r];
        if (lane == 0) {
            out[r]     = yv;
            out[H + r] = smemS[r];
        }
        if (bid == 0 && tid == 0) {
            out[2 * H]     = ponder;           // = haltstep = n-1
            out[2 * H + 1] = lastacc - 1.f;
        }
    } else {
        // never halted within 16 steps: halt_bin all zero
        int g = bid * THREADS + tid;
        if (g < H) { out[g] = 0.f; out[H + g] = 0.f; }
        if (g == 0) { out[2 * H] = ponder; out[2 * H + 1] = -1.f; }
    }
}

extern "C" void kernel_launch(void* const* d_in, const int* in_sizes, int n_in,
                              void* d_out, int out_size) {
    (void)in_sizes; (void)n_in; (void)out_size;
    // idempotent attribute set (not an allocation; safe pre-capture and in capture)
    cudaFuncSetAttribute(skiparnn_kernel,
                         cudaFuncAttributeMaxDynamicSharedMemorySize,
                         SMEM_FLOATS * (int)sizeof(float));
    skiparnn_kernel<<<GRID, THREADS, SMEM_FLOATS * sizeof(float)>>>(
        (const float*)d_in[0],  (const float*)d_in[1],
        (const float*)d_in[2],  (const float*)d_in[3],
        (const float*)d_in[4],  (const float*)d_in[5],
        (const float*)d_in[6],  (const float*)d_in[7],
        (const float*)d_in[8],  (const float*)d_in[9],
        (const float*)d_in[10], (const float*)d_in[11],
        (float*)d_out);
}